// round 1
// baseline (speedup 1.0000x reference)
#include <cuda_runtime.h>

#define N_PIX   6912
#define WIDTH   96
#define HEIGHT  72
#define CFEAT   16
#define TS      64                 // column tile size
#define NTILES  (N_PIX / TS)       // 108
#define GX      27                 // row blocks (27 * 256 = 6912)
#define GY      12                 // column splits (108 / 12 = 9 tiles each)

// Scratch (no allocations allowed): packed per-pixel records.
// rowrec: [x1.x, x1.y, x1.z, h1, f1n[16]]            -> 20 floats (5 x float4)
// colrec: [p2.x,p2.y,p2.z,h2, p2n.x,p2n.y,p2n.z,h2n, f2n[16]] -> 24 floats (6 x float4)
__device__ float g_rowrec[N_PIX * 20];
__device__ float g_colrec[N_PIX * 24];
__device__ float g_partials[GX * GY];
__device__ float g_fea[GX];

__global__ __launch_bounds__(256) void precompute_kernel(
    const float* __restrict__ f1, const float* __restrict__ f2,
    const float* __restrict__ dp1, const float* __restrict__ dp2,
    const float* __restrict__ pose, const float* __restrict__ noise)
{
    int i = blockIdx.x * 256 + threadIdx.x;

    // Compose noisy pose: pose_noisy = pose1_2 @ pose_noise (cheap per-thread).
    float PN[16];
#pragma unroll
    for (int r = 0; r < 4; r++)
#pragma unroll
        for (int c = 0; c < 4; c++) {
            float s = 0.0f;
#pragma unroll
            for (int k = 0; k < 4; k++) s = fmaf(pose[r * 4 + k], noise[k * 4 + c], s);
            PN[r * 4 + c] = s;
        }

    // yz1 = invK @ [u,v,1] = [1, (u-48)/48, (v-36)/48]
    int u = i % WIDTH, v = i / WIDTH;
    float y0 = 1.0f;
    float y1 = ((float)u - 48.0f) * (1.0f / 48.0f);
    float y2 = ((float)v - 36.0f) * (1.0f / 48.0f);

    float dd1 = dp1[i], dd2 = dp2[i];
    float x1x = y0 * dd1, x1y = y1 * dd1, x1z = y2 * dd1;
    float h1 = 0.5f * (x1x * x1x + x1y * x1y + x1z * x1z);

    float q0 = y0 * dd2, q1 = y1 * dd2, q2 = y2 * dd2;
    float p2[3], p2n[3];
#pragma unroll
    for (int r = 0; r < 3; r++) {
        p2[r]  = fmaf(pose[r * 4 + 0], q0, fmaf(pose[r * 4 + 1], q1,
                 fmaf(pose[r * 4 + 2], q2, pose[r * 4 + 3])));
        p2n[r] = fmaf(PN[r * 4 + 0], q0, fmaf(PN[r * 4 + 1], q1,
                 fmaf(PN[r * 4 + 2], q2, PN[r * 4 + 3])));
    }
    float h2  = 0.5f * (p2[0] * p2[0] + p2[1] * p2[1] + p2[2] * p2[2]);
    float h2n = 0.5f * (p2n[0] * p2n[0] + p2n[1] * p2n[1] + p2n[2] * p2n[2]);

    float a[CFEAT], b[CFEAT];
    float s1 = 0.0f, s2 = 0.0f;
#pragma unroll
    for (int c = 0; c < CFEAT; c++) { a[c] = f1[c * N_PIX + i]; s1 = fmaf(a[c], a[c], s1); }
#pragma unroll
    for (int c = 0; c < CFEAT; c++) { b[c] = f2[c * N_PIX + i]; s2 = fmaf(b[c], b[c], s2); }
    float n1 = sqrtf(s1), n2 = sqrtf(s2);
    float in1 = 1.0f / (n1 + 1e-8f), in2 = 1.0f / (n2 + 1e-8f);

    float* rr = g_rowrec + i * 20;
    rr[0] = x1x; rr[1] = x1y; rr[2] = x1z; rr[3] = h1;
#pragma unroll
    for (int c = 0; c < CFEAT; c++) rr[4 + c] = a[c] * in1;

    float* cc = g_colrec + i * 24;
    cc[0] = p2[0]; cc[1] = p2[1]; cc[2] = p2[2]; cc[3] = h2;
    cc[4] = p2n[0]; cc[5] = p2n[1]; cc[6] = p2n[2]; cc[7] = h2n;
#pragma unroll
    for (int c = 0; c < CFEAT; c++) cc[8 + c] = b[c] * in2;

    // Deterministic block reduction of feature norms.
    __shared__ float red[256];
    red[threadIdx.x] = n1 + n2;
    __syncthreads();
#pragma unroll
    for (int s = 128; s > 0; s >>= 1) {
        if (threadIdx.x < s) red[threadIdx.x] += red[threadIdx.x + s];
        __syncthreads();
    }
    if (threadIdx.x == 0) g_fea[blockIdx.x] = red[0];
}

__global__ __launch_bounds__(256) void main_kernel()
{
    __shared__ float4 sc[TS * 6];

    int m = blockIdx.x * 256 + threadIdx.x;
    const float4* rr = (const float4*)(g_rowrec + m * 20);
    float4 r0 = rr[0];                        // x1.x, x1.y, x1.z, h1
    float4 fa = rr[1], fb = rr[2], fc = rr[3], fd = rr[4];  // f1n[0..15]

    float acc = 0.0f;

    for (int t = blockIdx.y; t < NTILES; t += GY) {
        __syncthreads();
        const float4* src = (const float4*)g_colrec + (size_t)t * TS * 6;
#pragma unroll
        for (int i = threadIdx.x; i < TS * 6; i += 256) sc[i] = src[i];
        __syncthreads();

#pragma unroll 4
        for (int j = 0; j < TS; j++) {
            float4 P  = sc[j * 6 + 0];
            float4 Pn = sc[j * 6 + 1];
            float4 g0 = sc[j * 6 + 2];
            float4 g1 = sc[j * 6 + 3];
            float4 g2 = sc[j * 6 + 4];
            float4 g3 = sc[j * 6 + 5];

            // arg = x1.p2 - h1 - h2, clamped to <= 0 (matches max(d2,0))
            float a1 = fmaf(r0.x, P.x, fmaf(r0.y, P.y, fmaf(r0.z, P.z, -P.w))) - r0.w;
            float a2 = fmaf(r0.x, Pn.x, fmaf(r0.y, Pn.y, fmaf(r0.z, Pn.z, -Pn.w))) - r0.w;
            a1 = fminf(a1, 0.0f);
            a2 = fminf(a2, 0.0f);
            float e1 = __expf(a1);
            float e2 = __expf(a2);

            // gram dot, two accumulator chains for ILP
            float d0 = fa.x * g0.x;
            float d1 = fa.y * g0.y;
            d0 = fmaf(fa.z, g0.z, d0);  d1 = fmaf(fa.w, g0.w, d1);
            d0 = fmaf(fb.x, g1.x, d0);  d1 = fmaf(fb.y, g1.y, d1);
            d0 = fmaf(fb.z, g1.z, d0);  d1 = fmaf(fb.w, g1.w, d1);
            d0 = fmaf(fc.x, g2.x, d0);  d1 = fmaf(fc.y, g2.y, d1);
            d0 = fmaf(fc.z, g2.z, d0);  d1 = fmaf(fc.w, g2.w, d1);
            d0 = fmaf(fd.x, g3.x, d0);  d1 = fmaf(fd.y, g3.y, d1);
            d0 = fmaf(fd.z, g3.z, d0);  d1 = fmaf(fd.w, g3.w, d1);
            float g = d0 + d1;

            acc = fmaf(e1 - e2, g, acc);
        }
    }

    // Deterministic block reduction.
    __shared__ float red[256];
    __syncthreads();
    red[threadIdx.x] = acc;
    __syncthreads();
#pragma unroll
    for (int s = 128; s > 0; s >>= 1) {
        if (threadIdx.x < s) red[threadIdx.x] += red[threadIdx.x + s];
        __syncthreads();
    }
    if (threadIdx.x == 0) g_partials[blockIdx.x * GY + blockIdx.y] = red[0];
}

__global__ void finalize_kernel(float* out, int out_size)
{
    if (threadIdx.x == 0 && blockIdx.x == 0) {
        float S = 0.0f;
        for (int i = 0; i < GX * GY; i++) S += g_partials[i];
        float inner = -S / (float)N_PIX;   // gram carries the 1/N factor
        float F = 0.0f;
        for (int i = 0; i < GX; i++) F += g_fea[i];
        if (out_size > 0) out[0] = inner;        // final_loss (== inner_neg)
        if (out_size > 1) out[1] = inner;        // inner_neg
        if (out_size > 2) out[2] = F * 100.0f;   // fea_norm_sum
        for (int i = 3; i < out_size; i++) out[i] = 0.0f;
    }
}

extern "C" void kernel_launch(void* const* d_in, const int* in_sizes, int n_in,
                              void* d_out, int out_size)
{
    const float* f1    = (const float*)d_in[0];
    const float* f2    = (const float*)d_in[1];
    const float* dp1   = (const float*)d_in[2];
    const float* dp2   = (const float*)d_in[3];
    const float* pose  = (const float*)d_in[4];
    const float* noise = (const float*)d_in[5];

    precompute_kernel<<<GX, 256>>>(f1, f2, dp1, dp2, pose, noise);
    dim3 grid(GX, GY);
    main_kernel<<<grid, 256>>>();
    finalize_kernel<<<1, 32>>>((float*)d_out, out_size);
}

// round 2
// speedup vs baseline: 1.7014x; 1.7014x over previous
#include <cuda_runtime.h>

#define N_PIX   6912
#define WIDTH   96
#define CFEAT   16
#define TS      64                  // column tile size
#define NTILES  (N_PIX / TS)        // 108
#define RPT     3                   // rows per thread
#define BLK     128
#define GXM     18                  // 18 * 128 * 3 = 6912 rows
#define GYM     24                  // column splits
#define PRE_BLK 128
#define PRE_GRID (N_PIX / PRE_BLK)  // 54
#define LOG2E   1.4426950408889634f

typedef unsigned long long u64;

__device__ __forceinline__ u64 pk2(float lo, float hi) {
    u64 r; asm("mov.b64 %0, {%1, %2};" : "=l"(r) : "f"(lo), "f"(hi)); return r;
}
__device__ __forceinline__ void unpk2(float& lo, float& hi, u64 v) {
    asm("mov.b64 {%0, %1}, %2;" : "=f"(lo), "=f"(hi) : "l"(v));
}
__device__ __forceinline__ u64 fma2(u64 a, u64 b, u64 c) {
    u64 r; asm("fma.rn.f32x2 %0, %1, %2, %3;" : "=l"(r) : "l"(a), "l"(b), "l"(c)); return r;
}
__device__ __forceinline__ u64 mul2(u64 a, u64 b) {
    u64 r; asm("mul.rn.f32x2 %0, %1, %2;" : "=l"(r) : "l"(a), "l"(b)); return r;
}
__device__ __forceinline__ u64 add2(u64 a, u64 b) {
    u64 r; asm("add.rn.f32x2 %0, %1, %2;" : "=l"(r) : "l"(a), "l"(b)); return r;
}
__device__ __forceinline__ float ex2f(float a) {
    float r; asm("ex2.approx.ftz.f32 %0, %1;" : "=f"(r) : "f"(a)); return r;
}

// Scratch. colrec per pixel (24 floats = 6 float4):
// [Px, Pnx, Py, Pny | Pz, Pnz, -h2*L2E, -h2n*L2E | f2n/N x16]
__device__ float g_colrec[N_PIX * 24];
__device__ float g_part[GXM * GYM];
__device__ float g_fea1[GXM];
__device__ float g_fea2[PRE_GRID];

__global__ __launch_bounds__(PRE_BLK) void precompute_kernel(
    const float* __restrict__ f2, const float* __restrict__ dp2,
    const float* __restrict__ pose, const float* __restrict__ noise)
{
    int i = blockIdx.x * PRE_BLK + threadIdx.x;

    // pose_noisy = pose1_2 @ pose_noise
    float PN[12];
#pragma unroll
    for (int r = 0; r < 3; r++)
#pragma unroll
        for (int c = 0; c < 4; c++) {
            float s = 0.0f;
#pragma unroll
            for (int k = 0; k < 4; k++) s = fmaf(pose[r * 4 + k], noise[k * 4 + c], s);
            PN[r * 4 + c] = s;
        }

    int u = i % WIDTH, v = i / WIDTH;
    float y1 = ((float)u - 48.0f) * (1.0f / 48.0f);
    float y2 = ((float)v - 36.0f) * (1.0f / 48.0f);

    float d2 = dp2[i];
    float q0 = d2, q1 = y1 * d2, q2 = y2 * d2;
    float P[3], Pn[3];
#pragma unroll
    for (int r = 0; r < 3; r++) {
        P[r]  = fmaf(pose[r * 4 + 0], q0, fmaf(pose[r * 4 + 1], q1,
                fmaf(pose[r * 4 + 2], q2, pose[r * 4 + 3])));
        Pn[r] = fmaf(PN[r * 4 + 0], q0, fmaf(PN[r * 4 + 1], q1,
                fmaf(PN[r * 4 + 2], q2, PN[r * 4 + 3])));
    }
    float mh2  = -0.5f * LOG2E * (P[0] * P[0] + P[1] * P[1] + P[2] * P[2]);
    float mh2n = -0.5f * LOG2E * (Pn[0] * Pn[0] + Pn[1] * Pn[1] + Pn[2] * Pn[2]);

    float b[CFEAT], s2 = 0.0f;
#pragma unroll
    for (int c = 0; c < CFEAT; c++) { b[c] = f2[c * N_PIX + i]; s2 = fmaf(b[c], b[c], s2); }
    float n2 = sqrtf(s2);
    float sc = (1.0f / (n2 + 1e-8f)) * (1.0f / (float)N_PIX);

    float* cc = g_colrec + (size_t)i * 24;
    cc[0] = P[0]; cc[1] = Pn[0]; cc[2] = P[1]; cc[3] = Pn[1];
    cc[4] = P[2]; cc[5] = Pn[2]; cc[6] = mh2;  cc[7] = mh2n;
#pragma unroll
    for (int c = 0; c < CFEAT; c++) cc[8 + c] = b[c] * sc;

    __shared__ float red[PRE_BLK];
    red[threadIdx.x] = n2;
    __syncthreads();
#pragma unroll
    for (int s = PRE_BLK / 2; s > 0; s >>= 1) {
        if (threadIdx.x < s) red[threadIdx.x] += red[threadIdx.x + s];
        __syncthreads();
    }
    if (threadIdx.x == 0) g_fea2[blockIdx.x] = red[0];
}

__global__ __launch_bounds__(BLK) void main_kernel(
    const float* __restrict__ f1, const float* __restrict__ dp1)
{
    __shared__ ulonglong2 sc[TS * 6];   // 6 KB tile

    int tid = threadIdx.x;
    int base = blockIdx.x * (BLK * RPT);

    // Build row records in registers (exp2-domain scaled).
    u64 X[RPT], Y[RPT], Z[RPT], Hn[RPT], F[RPT][8];
    float fea1 = 0.0f;
#pragma unroll
    for (int k = 0; k < RPT; k++) {
        int m = base + k * BLK + tid;
        int u = m % WIDTH, v = m / WIDTH;
        float y1 = ((float)u - 48.0f) * (1.0f / 48.0f);
        float y2 = ((float)v - 36.0f) * (1.0f / 48.0f);
        float d = dp1[m];
        float xx = d, xy = y1 * d, xz = y2 * d;
        float h1 = 0.5f * (xx * xx + xy * xy + xz * xz);
        float xs = xx * LOG2E, ys = xy * LOG2E, zs = xz * LOG2E;
        X[k] = pk2(xs, xs); Y[k] = pk2(ys, ys); Z[k] = pk2(zs, zs);
        float hn = -h1 * LOG2E;
        Hn[k] = pk2(hn, hn);

        float a[CFEAT], s1 = 0.0f;
#pragma unroll
        for (int c = 0; c < CFEAT; c++) { a[c] = f1[c * N_PIX + m]; s1 = fmaf(a[c], a[c], s1); }
        float n1 = sqrtf(s1);
        fea1 += n1;
        float inv = 1.0f / (n1 + 1e-8f);
#pragma unroll
        for (int c = 0; c < 8; c++) F[k][c] = pk2(a[2 * c] * inv, a[2 * c + 1] * inv);
    }

    float acc[RPT];
#pragma unroll
    for (int k = 0; k < RPT; k++) acc[k] = 0.0f;

    for (int t = blockIdx.y; t < NTILES; t += GYM) {
        __syncthreads();
        const float4* src = (const float4*)g_colrec + (size_t)t * TS * 6;
        float4* dst = (float4*)sc;
#pragma unroll
        for (int i = tid; i < TS * 6; i += BLK) dst[i] = src[i];
        __syncthreads();

#pragma unroll 2
        for (int j = 0; j < TS; j++) {
            const ulonglong2* cp = sc + j * 6;
            ulonglong2 c0 = cp[0], c1 = cp[1];
            ulonglong2 c2 = cp[2], c3 = cp[3], c4 = cp[4], c5 = cp[5];
            u64 v0 = c0.x, v1 = c0.y, v2 = c1.x, hh = c1.y;

#pragma unroll
            for (int k = 0; k < RPT; k++) {
                u64 aa = fma2(X[k], v0, hh);
                aa = fma2(Y[k], v1, aa);
                aa = fma2(Z[k], v2, aa);
                aa = add2(aa, Hn[k]);
                float a1, a2; unpk2(a1, a2, aa);
                a1 = fminf(a1, 0.0f);
                a2 = fminf(a2, 0.0f);
                float e1 = ex2f(a1);
                float e2 = ex2f(a2);

                u64 dd = mul2(F[k][0], c2.x);
                dd = fma2(F[k][1], c2.y, dd);
                dd = fma2(F[k][2], c3.x, dd);
                dd = fma2(F[k][3], c3.y, dd);
                dd = fma2(F[k][4], c4.x, dd);
                dd = fma2(F[k][5], c4.y, dd);
                dd = fma2(F[k][6], c5.x, dd);
                dd = fma2(F[k][7], c5.y, dd);
                float g0, g1; unpk2(g0, g1, dd);
                acc[k] = fmaf(e1 - e2, g0 + g1, acc[k]);
            }
        }
    }

    __shared__ float red[BLK];
    float a = (acc[0] + acc[1]) + acc[2];
    __syncthreads();
    red[tid] = a;
    __syncthreads();
#pragma unroll
    for (int s = BLK / 2; s > 0; s >>= 1) {
        if (tid < s) red[tid] += red[tid + s];
        __syncthreads();
    }
    if (tid == 0) g_part[blockIdx.x * GYM + blockIdx.y] = red[0];

    if (blockIdx.y == 0) {
        __syncthreads();
        red[tid] = fea1;
        __syncthreads();
#pragma unroll
        for (int s = BLK / 2; s > 0; s >>= 1) {
            if (tid < s) red[tid] += red[tid + s];
            __syncthreads();
        }
        if (tid == 0) g_fea1[blockIdx.x] = red[0];
    }
}

__global__ void finalize_kernel(float* out, int out_size)
{
    int lane = threadIdx.x;  // 32 threads
    float S = 0.0f;
    for (int i = lane; i < GXM * GYM; i += 32) S += g_part[i];
    float Ff = 0.0f;
    for (int i = lane; i < GXM; i += 32) Ff += g_fea1[i];
    for (int i = lane; i < PRE_GRID; i += 32) Ff += g_fea2[i];
#pragma unroll
    for (int s = 16; s > 0; s >>= 1) {
        S  += __shfl_down_sync(0xFFFFFFFF, S, s);
        Ff += __shfl_down_sync(0xFFFFFFFF, Ff, s);
    }
    if (lane == 0) {
        float inner = -S;                        // 1/N folded into colrec features
        if (out_size > 0) out[0] = inner;        // final_loss
        if (out_size > 1) out[1] = inner;        // inner_neg
        if (out_size > 2) out[2] = Ff * 100.0f;  // fea_norm_sum
        for (int i = 3; i < out_size; i++) out[i] = 0.0f;
    }
}

extern "C" void kernel_launch(void* const* d_in, const int* in_sizes, int n_in,
                              void* d_out, int out_size)
{
    const float* f1    = (const float*)d_in[0];
    const float* f2    = (const float*)d_in[1];
    const float* dp1   = (const float*)d_in[2];
    const float* dp2   = (const float*)d_in[3];
    const float* pose  = (const float*)d_in[4];
    const float* noise = (const float*)d_in[5];

    precompute_kernel<<<PRE_GRID, PRE_BLK>>>(f2, dp2, pose, noise);
    dim3 grid(GXM, GYM);
    main_kernel<<<grid, BLK>>>(f1, dp1);
    finalize_kernel<<<1, 32>>>((float*)d_out, out_size);
}

// round 4
// speedup vs baseline: 1.7589x; 1.0338x over previous
#include <cuda_runtime.h>

#define N_PIX   6912
#define WIDTH   96
#define CFEAT   16
#define TS      64                  // column tile size
#define NTILES  (N_PIX / TS)        // 108
#define RPT     3                   // rows per thread
#define BLK     128
#define GXM     18                  // 18 * 128 * 3 = 6912 rows
#define GYM     36                  // column splits: 3 tiles per block, exact
#define PRE_BLK 64
#define PRE_GRID (N_PIX / PRE_BLK)  // 108
#define LOG2E   1.4426950408889634f

typedef unsigned long long u64;

__device__ __forceinline__ u64 pk2(float lo, float hi) {
    u64 r; asm("mov.b64 %0, {%1, %2};" : "=l"(r) : "f"(lo), "f"(hi)); return r;
}
__device__ __forceinline__ void unpk2(float& lo, float& hi, u64 v) {
    asm("mov.b64 {%0, %1}, %2;" : "=f"(lo), "=f"(hi) : "l"(v));
}
__device__ __forceinline__ u64 fma2(u64 a, u64 b, u64 c) {
    u64 r; asm("fma.rn.f32x2 %0, %1, %2, %3;" : "=l"(r) : "l"(a), "l"(b), "l"(c)); return r;
}
__device__ __forceinline__ u64 mul2(u64 a, u64 b) {
    u64 r; asm("mul.rn.f32x2 %0, %1, %2;" : "=l"(r) : "l"(a), "l"(b)); return r;
}
__device__ __forceinline__ float ex2f(float a) {
    float r; asm("ex2.approx.ftz.f32 %0, %1;" : "=f"(r) : "f"(a)); return r;
}

// colrec per pixel (24 floats = 6 float4):
// [Px, Pnx, Py, Pny | Pz, Pnz, -h2*L2E, -h2n*L2E | f2n/N x16]
__device__ float g_colrec[N_PIX * 24];
__device__ float g_part[GXM * GYM];
__device__ float g_fea1[GXM];
__device__ float g_fea2[PRE_GRID];

__global__ __launch_bounds__(PRE_BLK) void precompute_kernel(
    const float* __restrict__ f2, const float* __restrict__ dp2,
    const float* __restrict__ pose, const float* __restrict__ noise)
{
    int i = blockIdx.x * PRE_BLK + threadIdx.x;

    // pose_noisy = pose1_2 @ pose_noise (rows 0..2 only)
    float PN[12];
#pragma unroll
    for (int r = 0; r < 3; r++)
#pragma unroll
        for (int c = 0; c < 4; c++) {
            float s = 0.0f;
#pragma unroll
            for (int k = 0; k < 4; k++) s = fmaf(pose[r * 4 + k], noise[k * 4 + c], s);
            PN[r * 4 + c] = s;
        }

    int u = i % WIDTH, v = i / WIDTH;
    float y1 = ((float)u - 48.0f) * (1.0f / 48.0f);
    float y2 = ((float)v - 36.0f) * (1.0f / 48.0f);

    float d2 = dp2[i];
    float q0 = d2, q1 = y1 * d2, q2 = y2 * d2;
    float P[3], Pn[3];
#pragma unroll
    for (int r = 0; r < 3; r++) {
        P[r]  = fmaf(pose[r * 4 + 0], q0, fmaf(pose[r * 4 + 1], q1,
                fmaf(pose[r * 4 + 2], q2, pose[r * 4 + 3])));
        Pn[r] = fmaf(PN[r * 4 + 0], q0, fmaf(PN[r * 4 + 1], q1,
                fmaf(PN[r * 4 + 2], q2, PN[r * 4 + 3])));
    }
    float mh2  = -0.5f * LOG2E * (P[0] * P[0] + P[1] * P[1] + P[2] * P[2]);
    float mh2n = -0.5f * LOG2E * (Pn[0] * Pn[0] + Pn[1] * Pn[1] + Pn[2] * Pn[2]);

    float b[CFEAT], s2 = 0.0f;
#pragma unroll
    for (int c = 0; c < CFEAT; c++) { b[c] = f2[c * N_PIX + i]; s2 = fmaf(b[c], b[c], s2); }
    float n2 = sqrtf(s2);
    float sc = (1.0f / (n2 + 1e-8f)) * (1.0f / (float)N_PIX);

    float* cc = g_colrec + (size_t)i * 24;
    cc[0] = P[0]; cc[1] = Pn[0]; cc[2] = P[1]; cc[3] = Pn[1];
    cc[4] = P[2]; cc[5] = Pn[2]; cc[6] = mh2;  cc[7] = mh2n;
#pragma unroll
    for (int c = 0; c < CFEAT; c++) cc[8 + c] = b[c] * sc;

    __shared__ float red[PRE_BLK];
    red[threadIdx.x] = n2;
    __syncthreads();
#pragma unroll
    for (int s = PRE_BLK / 2; s > 0; s >>= 1) {
        if (threadIdx.x < s) red[threadIdx.x] += red[threadIdx.x + s];
        __syncthreads();
    }
    if (threadIdx.x == 0) g_fea2[blockIdx.x] = red[0];
}

__global__ __launch_bounds__(BLK) void main_kernel(
    const float* __restrict__ f1, const float* __restrict__ dp1)
{
    __shared__ ulonglong2 sc[TS * 6];   // 6 KB tile

    int tid = threadIdx.x;
    int base = blockIdx.x * (BLK * RPT);

    // Row records in registers (exp2-domain). h1 factored out of the pair loop:
    // e^{min(b-h1,0)} = e^{-h1} * e^{min(b,h1)}; row scaled once at the end.
    u64 X[RPT], Y[RPT], Z[RPT], F[RPT][8];
    float H1L[RPT], EH1[RPT];
    float fea1 = 0.0f;
#pragma unroll
    for (int k = 0; k < RPT; k++) {
        int m = base + k * BLK + tid;
        int u = m % WIDTH, v = m / WIDTH;
        float y1 = ((float)u - 48.0f) * (1.0f / 48.0f);
        float y2 = ((float)v - 36.0f) * (1.0f / 48.0f);
        float d = dp1[m];
        float xx = d, xy = y1 * d, xz = y2 * d;
        float h1L = 0.5f * LOG2E * (xx * xx + xy * xy + xz * xz);
        float xs = xx * LOG2E, ys = xy * LOG2E, zs = xz * LOG2E;
        X[k] = pk2(xs, xs); Y[k] = pk2(ys, ys); Z[k] = pk2(zs, zs);
        H1L[k] = h1L;
        EH1[k] = ex2f(-h1L);

        float a[CFEAT], s1 = 0.0f;
#pragma unroll
        for (int c = 0; c < CFEAT; c++) { a[c] = f1[c * N_PIX + m]; s1 = fmaf(a[c], a[c], s1); }
        float n1 = sqrtf(s1);
        fea1 += n1;
        float inv = 1.0f / (n1 + 1e-8f);
#pragma unroll
        for (int c = 0; c < 8; c++) F[k][c] = pk2(a[2 * c] * inv, a[2 * c + 1] * inv);
    }

    float acc[RPT];
#pragma unroll
    for (int k = 0; k < RPT; k++) acc[k] = 0.0f;

    for (int t = blockIdx.y; t < NTILES; t += GYM) {
        __syncthreads();
        const float4* src = (const float4*)g_colrec + (size_t)t * TS * 6;
        float4* dst = (float4*)sc;
#pragma unroll
        for (int i = tid; i < TS * 6; i += BLK) dst[i] = src[i];
        __syncthreads();

#pragma unroll 2
        for (int j = 0; j < TS; j++) {
            const ulonglong2* cp = sc + j * 6;
            ulonglong2 c0 = cp[0], c1 = cp[1];
            ulonglong2 c2 = cp[2], c3 = cp[3], c4 = cp[4], c5 = cp[5];
            u64 v0 = c0.x, v1 = c0.y, v2 = c1.x, hh = c1.y;   // hh = {-h2L, -h2nL}

#pragma unroll
            for (int k = 0; k < RPT; k++) {
                u64 aa = fma2(X[k], v0, hh);
                aa = fma2(Y[k], v1, aa);
                aa = fma2(Z[k], v2, aa);
                float b1, b2; unpk2(b1, b2, aa);
                b1 = fminf(b1, H1L[k]);
                b2 = fminf(b2, H1L[k]);
                float e1 = ex2f(b1);
                float e2 = ex2f(b2);

                u64 dd = mul2(F[k][0], c2.x);
                dd = fma2(F[k][1], c2.y, dd);
                dd = fma2(F[k][2], c3.x, dd);
                dd = fma2(F[k][3], c3.y, dd);
                dd = fma2(F[k][4], c4.x, dd);
                dd = fma2(F[k][5], c4.y, dd);
                dd = fma2(F[k][6], c5.x, dd);
                dd = fma2(F[k][7], c5.y, dd);
                float g0, g1; unpk2(g0, g1, dd);
                acc[k] = fmaf(e1 - e2, g0 + g1, acc[k]);
            }
        }
    }

    __shared__ float red[BLK];
    float a = fmaf(EH1[0], acc[0], fmaf(EH1[1], acc[1], EH1[2] * acc[2]));
    __syncthreads();
    red[tid] = a;
    __syncthreads();
#pragma unroll
    for (int s = BLK / 2; s > 0; s >>= 1) {
        if (tid < s) red[tid] += red[tid + s];
        __syncthreads();
    }
    if (tid == 0) g_part[blockIdx.x * GYM + blockIdx.y] = red[0];

    if (blockIdx.y == 0) {
        __syncthreads();
        red[tid] = fea1;
        __syncthreads();
#pragma unroll
        for (int s = BLK / 2; s > 0; s >>= 1) {
            if (tid < s) red[tid] += red[tid + s];
            __syncthreads();
        }
        if (tid == 0) g_fea1[blockIdx.x] = red[0];
    }
}

__global__ void finalize_kernel(float* out, int out_size)
{
    int lane = threadIdx.x;  // 32 threads
    float S = 0.0f;
    for (int i = lane; i < GXM * GYM; i += 32) S += g_part[i];
    float Ff = 0.0f;
    for (int i = lane; i < GXM; i += 32) Ff += g_fea1[i];
    for (int i = lane; i < PRE_GRID; i += 32) Ff += g_fea2[i];
#pragma unroll
    for (int s = 16; s > 0; s >>= 1) {
        S  += __shfl_down_sync(0xFFFFFFFF, S, s);
        Ff += __shfl_down_sync(0xFFFFFFFF, Ff, s);
    }
    if (lane == 0) {
        float inner = -S;                        // 1/N folded into colrec features
        if (out_size > 0) out[0] = inner;        // final_loss
        if (out_size > 1) out[1] = inner;        // inner_neg
        if (out_size > 2) out[2] = Ff * 100.0f;  // fea_norm_sum
        for (int i = 3; i < out_size; i++) out[i] = 0.0f;
    }
}

extern "C" void kernel_launch(void* const* d_in, const int* in_sizes, int n_in,
                              void* d_out, int out_size)
{
    const float* f1    = (const float*)d_in[0];
    const float* f2    = (const float*)d_in[1];
    const float* dp1   = (const float*)d_in[2];
    const float* dp2   = (const float*)d_in[3];
    const float* pose  = (const float*)d_in[4];
    const float* noise = (const float*)d_in[5];

    precompute_kernel<<<PRE_GRID, PRE_BLK>>>(f2, dp2, pose, noise);
    dim3 grid(GXM, GYM);
    main_kernel<<<grid, BLK>>>(f1, dp1);
    finalize_kernel<<<1, 32>>>((float*)d_out, out_size);
}